// round 12
// baseline (speedup 1.0000x reference)
#include <cuda_runtime.h>
#include <cuda_bf16.h>
#include <math.h>

// Problem dims (fixed by the reference)
#define BB 16
#define TT 4096
#define HH 1024
#define KK 128
#define VV 128
#define OO 128
#define PP 512            // 3K + V
#define MM (BB * TT)      // 65536

// Scratch (static device globals: allocation-free, graph-capturable)
__device__ float g_qkgv[(size_t)BB * TT * PP];   // 128 MB activated projections
__device__ float g_obuf[(size_t)BB * TT * VV];   // 32 MB pre-projection readout
__device__ float g_cdump[(size_t)BB * KK * VV];  // fallback c_final sink
__device__ __nv_bfloat16 g_ahi[(size_t)MM * HH]; // hidden split hi
__device__ __nv_bfloat16 g_alo[(size_t)MM * HH]; // hidden split lo
__device__ __nv_bfloat16 g_whi[(size_t)PP * HH];
__device__ __nv_bfloat16 g_wlo[(size_t)PP * HH];

typedef unsigned long long ull;

// ---------------------------------------------------------------------------
// small PTX helpers
// ---------------------------------------------------------------------------
__device__ __forceinline__ unsigned smem_u32(const void* p) {
    return (unsigned)__cvta_generic_to_shared(p);
}
__device__ __forceinline__ void cp16(void* dst, const void* src) {
    asm volatile("cp.async.cg.shared.global [%0], [%1], 16;\n"
                 :: "r"(smem_u32(dst)), "l"(src));
}
__device__ __forceinline__ void cp_commit() {
    asm volatile("cp.async.commit_group;\n");
}
__device__ __forceinline__ void cp_wait1() {
    asm volatile("cp.async.wait_group 1;\n");
}
__device__ __forceinline__ void cp_wait5() {
    asm volatile("cp.async.wait_group 5;\n");
}
__device__ __forceinline__ void ldsm4(unsigned r[4], const void* p) {
    unsigned a = smem_u32(p);
    asm volatile("ldmatrix.sync.aligned.m8n8.x4.shared.b16 {%0,%1,%2,%3}, [%4];\n"
                 : "=r"(r[0]), "=r"(r[1]), "=r"(r[2]), "=r"(r[3]) : "r"(a));
}
__device__ __forceinline__ void mma16816(float d[4], const unsigned a[4],
                                         unsigned b0, unsigned b1) {
    asm volatile("mma.sync.aligned.m16n8k16.row.col.f32.bf16.bf16.f32 "
                 "{%0,%1,%2,%3}, {%4,%5,%6,%7}, {%8,%9}, {%0,%1,%2,%3};\n"
                 : "+f"(d[0]), "+f"(d[1]), "+f"(d[2]), "+f"(d[3])
                 : "r"(a[0]), "r"(a[1]), "r"(a[2]), "r"(a[3]), "r"(b0), "r"(b1));
}
__device__ __forceinline__ unsigned short bfbits(__nv_bfloat16 h) {
    return ((__nv_bfloat16_raw)h).x;
}

// ---- packed f32x2 helpers (PTX-only; base sm_100 feature) ----
__device__ __forceinline__ ull pk2(float lo, float hi) {
    ull r;
    asm("mov.b64 %0, {%1, %2};" : "=l"(r) : "f"(lo), "f"(hi));
    return r;
}
__device__ __forceinline__ void unpk2(ull d, float& lo, float& hi) {
    asm("mov.b64 {%0, %1}, %2;" : "=f"(lo), "=f"(hi) : "l"(d));
}
__device__ __forceinline__ ull mul2(ull a, ull b) {
    ull r;
    asm("mul.rn.f32x2 %0, %1, %2;" : "=l"(r) : "l"(a), "l"(b));
    return r;
}
__device__ __forceinline__ ull fma2(ull a, ull b, ull c) {
    ull r;
    asm("fma.rn.f32x2 %0, %1, %2, %3;" : "=l"(r) : "l"(a), "l"(b), "l"(c));
    return r;
}

// ---------------------------------------------------------------------------
// fp32 -> (hi, lo) bf16 split. x = hi + lo + O(2^-16 |x|).
// ---------------------------------------------------------------------------
__global__ __launch_bounds__(256) void cvt_hilo(
    const float* __restrict__ x, __nv_bfloat16* __restrict__ hi,
    __nv_bfloat16* __restrict__ lo, int n4)
{
    int i = blockIdx.x * blockDim.x + threadIdx.x;
    if (i >= n4) return;
    float4 xv = ((const float4*)x)[i];
    float xs[4] = {xv.x, xv.y, xv.z, xv.w};
    unsigned short hb[4], lb[4];
#pragma unroll
    for (int j = 0; j < 4; ++j) {
        __nv_bfloat16 h = __float2bfloat16(xs[j]);
        float r = xs[j] - __bfloat162float(h);   // exact residual
        __nv_bfloat16 l = __float2bfloat16(r);
        hb[j] = bfbits(h);
        lb[j] = bfbits(l);
    }
    uint2 uh = make_uint2(hb[0] | ((unsigned)hb[1] << 16),
                          hb[2] | ((unsigned)hb[3] << 16));
    uint2 ul = make_uint2(lb[0] | ((unsigned)lb[1] << 16),
                          lb[2] | ((unsigned)lb[3] << 16));
    ((uint2*)hi)[i] = uh;
    ((uint2*)lo)[i] = ul;
}

// ---------------------------------------------------------------------------
// GEMM1 (round-9 known-good): qkgv[M,512] = act( A @ W^T + bias )
// bf16 hi/lo split, 3-term mma.sync (hh + hl + lh) ~ fp32 accuracy.
// CTA tile 128x128, BK=32, 8 warps (4m x 2n, warp tile 32x64),
// cp.async 3-stage ring, ldmatrix fragments, pad-40 smem rows.
// ---------------------------------------------------------------------------
#define G1_STRIDE 40                       // bf16 elems per smem row (32 + 8 pad)
#define G1_PLANE  (128 * G1_STRIDE)        // 5120 bf16
#define G1_STAGE  (4 * G1_PLANE)           // Ah, Al, Wh, Wl
#define G1_SMEM   (3 * G1_STAGE * 2)       // bytes = 122880

__global__ __launch_bounds__(256) void gemm1_mma(
    const __nv_bfloat16* __restrict__ Ah, const __nv_bfloat16* __restrict__ Al,
    const __nv_bfloat16* __restrict__ Wh, const __nv_bfloat16* __restrict__ Wl,
    const float* __restrict__ bias, float* __restrict__ C)
{
    extern __shared__ __nv_bfloat16 sm[];
    const int tid  = threadIdx.x;
    const int m0   = blockIdx.y << 7;
    const int n0   = blockIdx.x << 7;
    const int lane = tid & 31;
    const int warp = tid >> 5;
    const int wm   = (warp & 3) << 5;      // warp m offset
    const int wn   = (warp >> 2) << 6;     // warp n offset

    const __nv_bfloat16* srcs[4] = {
        Ah + (size_t)m0 * HH, Al + (size_t)m0 * HH,
        Wh + (size_t)n0 * HH, Wl + (size_t)n0 * HH };

    auto issue = [&](int kt, int st) {
        __nv_bfloat16* sb = sm + st * G1_STAGE;
#pragma unroll
        for (int p = 0; p < 4; ++p) {
            const __nv_bfloat16* g = srcs[p] + kt * 32;
            __nv_bfloat16* sp = sb + p * G1_PLANE;
#pragma unroll
            for (int h = 0; h < 2; ++h) {
                int c = tid + (h << 8);              // 0..511 chunks of 16B
                int row = c >> 2, col = (c & 3) << 3;
                cp16(sp + row * G1_STRIDE + col, g + (size_t)row * HH + col);
            }
        }
    };

    float acc[2][8][4];
#pragma unroll
    for (int im = 0; im < 2; ++im)
#pragma unroll
        for (int j = 0; j < 8; ++j)
#pragma unroll
            for (int r = 0; r < 4; ++r) acc[im][j][r] = 0.f;

    issue(0, 0); cp_commit();
    issue(1, 1); cp_commit();

    // fragment address components (ldmatrix lane -> row/col)
    const int arow  = lane & 15;
    const int acolb = (lane >> 4) << 3;
    const int brow  = ((lane & 16) >> 1) + (lane & 7);
    const int bcolb = ((lane >> 3) & 1) << 3;

    const int nk = HH / 32;                // 32
    for (int kt = 0; kt < nk; ++kt) {
        cp_wait1();
        __syncthreads();
        const __nv_bfloat16* st  = sm + (kt % 3) * G1_STAGE;
        const __nv_bfloat16* sAh = st;
        const __nv_bfloat16* sAl = st + G1_PLANE;
        const __nv_bfloat16* sWh = st + 2 * G1_PLANE;
        const __nv_bfloat16* sWl = st + 3 * G1_PLANE;
#pragma unroll
        for (int ks = 0; ks < 2; ++ks) {
            const int ko = ks << 4;
            unsigned aH[2][4], aL[2][4];
#pragma unroll
            for (int im = 0; im < 2; ++im) {
                int r = wm + (im << 4) + arow;
                ldsm4(aH[im], sAh + r * G1_STRIDE + ko + acolb);
                ldsm4(aL[im], sAl + r * G1_STRIDE + ko + acolb);
            }
#pragma unroll
            for (int ng = 0; ng < 4; ++ng) {
                int r = wn + (ng << 4) + brow;
                unsigned bh[4], bl[4];
                ldsm4(bh, sWh + r * G1_STRIDE + ko + bcolb);
                ldsm4(bl, sWl + r * G1_STRIDE + ko + bcolb);
#pragma unroll
                for (int im = 0; im < 2; ++im) {
                    mma16816(acc[im][ng * 2],     aH[im], bh[0], bh[1]);
                    mma16816(acc[im][ng * 2 + 1], aH[im], bh[2], bh[3]);
                    mma16816(acc[im][ng * 2],     aH[im], bl[0], bl[1]);
                    mma16816(acc[im][ng * 2 + 1], aH[im], bl[2], bl[3]);
                    mma16816(acc[im][ng * 2],     aL[im], bh[0], bh[1]);
                    mma16816(acc[im][ng * 2 + 1], aL[im], bh[2], bh[3]);
                }
            }
        }
        // safe: stage (kt+2)%3 == (kt-1)%3 was last read in iter kt-1,
        // protected by this iteration's barrier (3-stage ring).
        if (kt + 2 < nk) issue(kt + 2, (kt + 2) % 3);
        cp_commit();
    }

    // epilogue: bias + per-128-col-block activation (q:id, k:sig, g:sig, v:tanh)
    const int act = (n0 >= 384) ? 2 : ((n0 >= 128) ? 1 : 0);
    const int r0     = m0 + wm + (lane >> 2);
    const int c0base = n0 + wn + ((lane & 3) << 1);
#pragma unroll
    for (int j = 0; j < 8; ++j) {
        int col = c0base + (j << 3);
        float b0 = bias[col], b1 = bias[col + 1];
#pragma unroll
        for (int im = 0; im < 2; ++im) {
            int rb = r0 + (im << 4);
            float v0 = acc[im][j][0] + b0, v1 = acc[im][j][1] + b1;
            float v2 = acc[im][j][2] + b0, v3 = acc[im][j][3] + b1;
            if (act == 1) {
                v0 = 1.f / (1.f + __expf(-v0)); v1 = 1.f / (1.f + __expf(-v1));
                v2 = 1.f / (1.f + __expf(-v2)); v3 = 1.f / (1.f + __expf(-v3));
            } else if (act == 2) {
                v0 = tanhf(v0); v1 = tanhf(v1); v2 = tanhf(v2); v3 = tanhf(v3);
            }
            *(float2*)(C + (size_t)rb * PP + col)       = make_float2(v0, v1);
            *(float2*)(C + (size_t)(rb + 8) * PP + col) = make_float2(v2, v3);
        }
    }
}

// ---------------------------------------------------------------------------
// Sequential scan with packed f32x2 math.
// Grid (batch=16, v-tile=8), 256 threads = 8 warps.
// Warp w owns v pair {v0+2w, v0+2w+1}; lane l owns k rows 4l..4l+3.
// State packed over k-pairs: cP[v][kp] = (c[k0],c[k1]) as f32x2 in one 64-bit
// reg. q/k/g packs come directly from float4 loads (free register pairing);
// only the v broadcast needs 2 explicit packs per step.
// Per step: 4 mul2 + 4 fma2 (update) + 2 mul2 + 2 fma2 (readout) + 2 hsum
// = ~12 math ops vs 24 scalar. Ring/shfl/barrier structure unchanged.
// ---------------------------------------------------------------------------
#define SC_GROUPS 7
#define SC_STAGES (SC_GROUPS * 4)      // 28

__global__ __launch_bounds__(256) void scan_kernel(
    const float* __restrict__ qkgv, float* __restrict__ obuf,
    float* __restrict__ cfin)
{
    const int b   = blockIdx.x;
    const int v0  = blockIdx.y << 4;
    const int tid = threadIdx.x;
    const int w   = tid >> 5;            // warp: v pair {2w, 2w+1} within tile
    const int l   = tid & 31;            // lane: k rows 4l..4l+3
    const int k0  = l << 2;

    __shared__ float s[SC_STAGES][400];  // [q:128 | k:128 | g:128 | v-tile:16]

    const float* base = qkgv + (size_t)b * TT * PP;
    float* ob = obuf + (size_t)b * TT * VV + v0 + (w << 1);

    // packed state: cP[v][kpair]
    ull cP[2][2];
    cP[0][0] = cP[0][1] = cP[1][0] = cP[1][1] = 0ULL;   // (0.f,0.f)

    // 100 copy threads x 16B per step
    const bool cpr = (tid < 100);
    const int goff = (tid < 96) ? (tid << 2) : (384 + v0 + ((tid - 96) << 2));
    const int soff = (tid < 96) ? (tid << 2) : (384 + ((tid - 96) << 2));

    auto issue_group = [&](int g) {
        if (cpr) {
            const int sb = (g % SC_GROUPS) << 2;
            const float* p = base + (size_t)(g << 2) * PP + goff;
#pragma unroll
            for (int i = 0; i < 4; ++i)
                cp16(&s[sb + i][soff], p + (size_t)i * PP);
        }
        cp_commit();
    };

#pragma unroll
    for (int g = 0; g < 6; ++g) issue_group(g);

    const int NG = TT / 4;               // 1024 groups
    for (int g = 0; g < NG; ++g) {
        cp_wait5();
        __syncthreads();

        const int sb = (g % SC_GROUPS) << 2;

        // batch-load all 4 steps' operands (one exposed LDS latency)
        float4 qr[4], kr[4], gr[4]; float2 vr[4];
#pragma unroll
        for (int i = 0; i < 4; ++i) {
            const float* st = s[sb + i];
            qr[i] = *(const float4*)&st[k0];
            kr[i] = *(const float4*)&st[128 + k0];
            gr[i] = *(const float4*)&st[256 + k0];
            vr[i] = *(const float2*)&st[384 + (w << 1)];
        }

        float a0[4], a1[4];
#pragma unroll
        for (int i = 0; i < 4; ++i) {
            const ull q01 = pk2(qr[i].x, qr[i].y), q23 = pk2(qr[i].z, qr[i].w);
            const ull k01 = pk2(kr[i].x, kr[i].y), k23 = pk2(kr[i].z, kr[i].w);
            const ull g01 = pk2(gr[i].x, gr[i].y), g23 = pk2(gr[i].z, gr[i].w);
            const ull vv0 = pk2(vr[i].x, vr[i].x);
            const ull vv1 = pk2(vr[i].y, vr[i].y);

            // state update: c = c*g + k*v (packed over k-pairs)
            cP[0][0] = fma2(cP[0][0], g01, mul2(k01, vv0));
            cP[0][1] = fma2(cP[0][1], g23, mul2(k23, vv0));
            cP[1][0] = fma2(cP[1][0], g01, mul2(k01, vv1));
            cP[1][1] = fma2(cP[1][1], g23, mul2(k23, vv1));

            // readout: acc = sum_k c*q  (packed partials, then horizontal)
            ull t0 = fma2(cP[0][0], q01, mul2(cP[0][1], q23));
            ull t1 = fma2(cP[1][0], q01, mul2(cP[1][1], q23));
            float x0, x1, y0, y1;
            unpk2(t0, x0, x1);
            unpk2(t1, y0, y1);
            a0[i] = x0 + x1;
            a1[i] = y0 + y1;
        }

        // 8 interleaved full-warp butterflies (reduce over k: all 32 lanes)
#pragma unroll
        for (int d = 1; d < 32; d <<= 1) {
#pragma unroll
            for (int i = 0; i < 4; ++i) {
                a0[i] += __shfl_xor_sync(0xffffffffu, a0[i], d);
                a1[i] += __shfl_xor_sync(0xffffffffu, a1[i], d);
            }
        }
        if (l == 0) {
            const size_t t4 = (size_t)(g << 2) * VV;
#pragma unroll
            for (int i = 0; i < 4; ++i)
                *(float2*)&ob[t4 + (size_t)i * VV] = make_float2(a0[i], a1[i]);
        }

        // refill: group g+6 -> slots of group g-1 (readers passed top barrier)
        if (g + 6 < NG) issue_group(g + 6);
        else            cp_commit();     // keep per-thread group counts uniform
    }

    // c_final: (B, K, V). Thread owns k rows 4l..4l+3, v cols v0+2w..+1.
    float c00, c01, c02, c03, c10, c11, c12, c13;
    unpk2(cP[0][0], c00, c01);  unpk2(cP[0][1], c02, c03);
    unpk2(cP[1][0], c10, c11);  unpk2(cP[1][1], c12, c13);
    float cv0[4] = {c00, c01, c02, c03};
    float cv1[4] = {c10, c11, c12, c13};
#pragma unroll
    for (int i = 0; i < 4; ++i)
        *(float2*)&cfin[((size_t)b * KK + (k0 + i)) * VV + v0 + (w << 1)] =
            make_float2(cv0[i], cv1[i]);
}

// ---------------------------------------------------------------------------
// GEMM2 (small): fp32 SIMT TN GEMM, 128x128 tile, BK=16.
// ---------------------------------------------------------------------------
__global__ __launch_bounds__(256) void gemm_tn(
    const float* __restrict__ A, const float* __restrict__ W,
    const float* __restrict__ bias, float* __restrict__ C,
    int M, int N, int Kd)
{
    __shared__ float As[2][16][136];
    __shared__ float Bs[2][16][136];

    const int tid = threadIdx.x;
    const int m0 = blockIdx.y << 7;
    const int n0 = blockIdx.x << 7;
    const int lr = tid >> 1;
    const int lc = (tid & 1) << 3;

    const float* Aptr = A + (size_t)(m0 + lr) * Kd + lc;
    const float* Wptr = W + (size_t)(n0 + lr) * Kd + lc;

    {
        float4 a0 = *(const float4*)Aptr;
        float4 a1 = *(const float4*)(Aptr + 4);
        float4 b0 = *(const float4*)Wptr;
        float4 b1 = *(const float4*)(Wptr + 4);
#pragma unroll
        for (int cc = 0; cc < 4; ++cc) {
            As[0][lc + cc][lr]     = ((const float*)&a0)[cc];
            As[0][lc + 4 + cc][lr] = ((const float*)&a1)[cc];
            Bs[0][lc + cc][lr]     = ((const float*)&b0)[cc];
            Bs[0][lc + 4 + cc][lr] = ((const float*)&b1)[cc];
        }
    }
    __syncthreads();

    const int ty  = tid >> 4;
    const int tx  = tid & 15;
    const int ar0 = ty << 2;
    const int bc0 = tx << 2;

    float acc[8][8];
#pragma unroll
    for (int i = 0; i < 8; ++i)
#pragma unroll
        for (int j = 0; j < 8; ++j) acc[i][j] = 0.f;

    const int nk = Kd >> 4;
    for (int kt = 0; kt < nk; ++kt) {
        const int buf = kt & 1;
        float4 pa0, pa1, pb0, pb1;
        const bool pf = (kt + 1) < nk;
        if (pf) {
            const float* Ap = Aptr + ((kt + 1) << 4);
            const float* Wp = Wptr + ((kt + 1) << 4);
            pa0 = *(const float4*)Ap;  pa1 = *(const float4*)(Ap + 4);
            pb0 = *(const float4*)Wp;  pb1 = *(const float4*)(Wp + 4);
        }
#pragma unroll
        for (int kk = 0; kk < 16; ++kk) {
            float4 a0 = *(const float4*)&As[buf][kk][ar0];
            float4 a1 = *(const float4*)&As[buf][kk][64 + ar0];
            float4 b0 = *(const float4*)&Bs[buf][kk][bc0];
            float4 b1 = *(const float4*)&Bs[buf][kk][64 + bc0];
            float af[8] = {a0.x,a0.y,a0.z,a0.w,a1.x,a1.y,a1.z,a1.w};
            float bf[8] = {b0.x,b0.y,b0.z,b0.w,b1.x,b1.y,b1.z,b1.w};
#pragma unroll
            for (int i = 0; i < 8; ++i)
#pragma unroll
                for (int j = 0; j < 8; ++j)
                    acc[i][j] = fmaf(af[i], bf[j], acc[i][j]);
        }
        if (pf) {
            const int nb = buf ^ 1;
#pragma unroll
            for (int cc = 0; cc < 4; ++cc) {
                As[nb][lc + cc][lr]     = ((const float*)&pa0)[cc];
                As[nb][lc + 4 + cc][lr] = ((const float*)&pa1)[cc];
                Bs[nb][lc + cc][lr]     = ((const float*)&pb0)[cc];
                Bs[nb][lc + 4 + cc][lr] = ((const float*)&pb1)[cc];
            }
        }
        __syncthreads();
    }

    float bv[8];
#pragma unroll
    for (int j = 0; j < 8; ++j) {
        int n = n0 + ((j < 4) ? (bc0 + j) : (64 + bc0 + (j - 4)));
        bv[j] = bias[n];
    }
#pragma unroll
    for (int i = 0; i < 8; ++i) {
        int m = m0 + ((i < 4) ? (ar0 + i) : (64 + ar0 + (i - 4)));
        float o[8];
#pragma unroll
        for (int j = 0; j < 8; ++j) o[j] = acc[i][j] + bv[j];
        float* cp = C + (size_t)m * N + n0;
        *(float4*)(cp + bc0)      = make_float4(o[0], o[1], o[2], o[3]);
        *(float4*)(cp + 64 + bc0) = make_float4(o[4], o[5], o[6], o[7]);
    }
}

// ---------------------------------------------------------------------------
extern "C" void kernel_launch(void* const* d_in, const int* in_sizes, int n_in,
                              void* d_out, int out_size)
{
    const float* hidden = (const float*)d_in[0];  // (B,T,H)
    const float* W_proj = (const float*)d_in[1];  // (3K+V, H)
    const float* b_proj = (const float*)d_in[2];  // (3K+V,)
    const float* W_out  = (const float*)d_in[3];  // (O, V)
    const float* b_out  = (const float*)d_in[4];  // (O,)
    float* out = (float*)d_out;

    float *qkgv, *obuf, *cdump;
    __nv_bfloat16 *ahi, *alo, *whi, *wlo;
    cudaGetSymbolAddress((void**)&qkgv,  g_qkgv);
    cudaGetSymbolAddress((void**)&obuf,  g_obuf);
    cudaGetSymbolAddress((void**)&cdump, g_cdump);
    cudaGetSymbolAddress((void**)&ahi,   g_ahi);
    cudaGetSymbolAddress((void**)&alo,   g_alo);
    cudaGetSymbolAddress((void**)&whi,   g_whi);
    cudaGetSymbolAddress((void**)&wlo,   g_wlo);

    const size_t out_main = (size_t)BB * TT * OO;
    const size_t out_full = out_main + (size_t)BB * KK * VV;
    float* cfin = ((size_t)out_size >= out_full) ? (out + out_main) : cdump;

    // 0) fp32 -> bf16 hi/lo splits
    {
        int n4 = (MM * HH) / 4;                     // 16,777,216
        cvt_hilo<<<(n4 + 255) / 256, 256>>>(hidden, ahi, alo, n4);
        int w4 = (PP * HH) / 4;                     // 131,072
        cvt_hilo<<<(w4 + 255) / 256, 256>>>(W_proj, whi, wlo, w4);
    }
    // 1) fused projection GEMM (mma.sync, 3-term bf16 split) + activations
    {
        cudaFuncSetAttribute(gemm1_mma,
                             cudaFuncAttributeMaxDynamicSharedMemorySize, G1_SMEM);
        dim3 grid(PP / 128, MM / 128);              // (4, 512)
        gemm1_mma<<<grid, 256, G1_SMEM>>>(ahi, alo, whi, wlo, b_proj, qkgv);
    }
    // 2) sequential gated fast-weight scan (f32x2 packed)
    {
        dim3 grid(BB, VV / 16);                     // (16, 8)
        scan_kernel<<<grid, 256>>>(qkgv, obuf, cfin);
    }
    // 3) output projection
    {
        dim3 grid(OO / 128, MM / 128);              // (1, 512)
        gemm_tn<<<grid, 256>>>(obuf, W_out, b_out, out, MM, OO, VV);
    }
}

// round 13
// speedup vs baseline: 1.0859x; 1.0859x over previous
#include <cuda_runtime.h>
#include <cuda_bf16.h>
#include <math.h>

// Problem dims (fixed by the reference)
#define BB 16
#define TT 4096
#define HH 1024
#define KK 128
#define VV 128
#define OO 128
#define PP 512            // 3K + V
#define MM (BB * TT)      // 65536

// Scratch (static device globals: allocation-free, graph-capturable)
__device__ float g_qkgv[(size_t)BB * TT * PP];   // 128 MB activated projections
__device__ float g_obuf[(size_t)BB * TT * VV];   // 32 MB pre-projection readout
__device__ float g_cdump[(size_t)BB * KK * VV];  // fallback c_final sink
__device__ __nv_bfloat16 g_ahi[(size_t)MM * HH]; // hidden split hi
__device__ __nv_bfloat16 g_alo[(size_t)MM * HH]; // hidden split lo
__device__ __nv_bfloat16 g_whi[(size_t)PP * HH];
__device__ __nv_bfloat16 g_wlo[(size_t)PP * HH];

typedef unsigned long long ull;

// ---------------------------------------------------------------------------
// small PTX helpers
// ---------------------------------------------------------------------------
__device__ __forceinline__ unsigned smem_u32(const void* p) {
    return (unsigned)__cvta_generic_to_shared(p);
}
__device__ __forceinline__ void cp16(void* dst, const void* src) {
    asm volatile("cp.async.cg.shared.global [%0], [%1], 16;\n"
                 :: "r"(smem_u32(dst)), "l"(src));
}
__device__ __forceinline__ void cp_commit() {
    asm volatile("cp.async.commit_group;\n");
}
__device__ __forceinline__ void cp_wait1() {
    asm volatile("cp.async.wait_group 1;\n");
}
__device__ __forceinline__ void ldsm4(unsigned r[4], const void* p) {
    unsigned a = smem_u32(p);
    asm volatile("ldmatrix.sync.aligned.m8n8.x4.shared.b16 {%0,%1,%2,%3}, [%4];\n"
                 : "=r"(r[0]), "=r"(r[1]), "=r"(r[2]), "=r"(r[3]) : "r"(a));
}
__device__ __forceinline__ void mma16816(float d[4], const unsigned a[4],
                                         unsigned b0, unsigned b1) {
    asm volatile("mma.sync.aligned.m16n8k16.row.col.f32.bf16.bf16.f32 "
                 "{%0,%1,%2,%3}, {%4,%5,%6,%7}, {%8,%9}, {%0,%1,%2,%3};\n"
                 : "+f"(d[0]), "+f"(d[1]), "+f"(d[2]), "+f"(d[3])
                 : "r"(a[0]), "r"(a[1]), "r"(a[2]), "r"(a[3]), "r"(b0), "r"(b1));
}
__device__ __forceinline__ unsigned short bfbits(__nv_bfloat16 h) {
    return ((__nv_bfloat16_raw)h).x;
}

// ---------------------------------------------------------------------------
// fp32 -> (hi, lo) bf16 split. x = hi + lo + O(2^-16 |x|).
// ---------------------------------------------------------------------------
__global__ __launch_bounds__(256) void cvt_hilo(
    const float* __restrict__ x, __nv_bfloat16* __restrict__ hi,
    __nv_bfloat16* __restrict__ lo, int n4)
{
    int i = blockIdx.x * blockDim.x + threadIdx.x;
    if (i >= n4) return;
    float4 xv = ((const float4*)x)[i];
    float xs[4] = {xv.x, xv.y, xv.z, xv.w};
    unsigned short hb[4], lb[4];
#pragma unroll
    for (int j = 0; j < 4; ++j) {
        __nv_bfloat16 h = __float2bfloat16(xs[j]);
        float r = xs[j] - __bfloat162float(h);   // exact residual
        __nv_bfloat16 l = __float2bfloat16(r);
        hb[j] = bfbits(h);
        lb[j] = bfbits(l);
    }
    uint2 uh = make_uint2(hb[0] | ((unsigned)hb[1] << 16),
                          hb[2] | ((unsigned)hb[3] << 16));
    uint2 ul = make_uint2(lb[0] | ((unsigned)lb[1] << 16),
                          lb[2] | ((unsigned)lb[3] << 16));
    ((uint2*)hi)[i] = uh;
    ((uint2*)lo)[i] = ul;
}

// ---------------------------------------------------------------------------
// GEMM1 v2: qkgv[M,512] = act( A[M,1024] @ W[512,1024]^T + bias )
// bf16 hi/lo split, 3-term mma.sync. CTA tile 128m x 256n (N-fused: halves
// A L2 traffic), BK=32, 8 warps (4m x 2n), warp tile 32x128 (acc 128 regs).
// cp.async 3-stage ring, ldmatrix, pad-40 smem rows.
// ---------------------------------------------------------------------------
#define G1_STRIDE 40                       // bf16 per smem row (32 + 8 pad)
#define G1_PLANE_A (128 * G1_STRIDE)       // 5120 bf16
#define G1_PLANE_W (256 * G1_STRIDE)       // 10240 bf16
#define G1_STAGE  (2 * G1_PLANE_A + 2 * G1_PLANE_W)   // 30720 bf16
#define G1_SMEM   (3 * G1_STAGE * 2)       // 184320 B

__global__ __launch_bounds__(256) void gemm1_mma(
    const __nv_bfloat16* __restrict__ Ah, const __nv_bfloat16* __restrict__ Al,
    const __nv_bfloat16* __restrict__ Wh, const __nv_bfloat16* __restrict__ Wl,
    const float* __restrict__ bias, float* __restrict__ C)
{
    extern __shared__ __nv_bfloat16 sm[];
    const int tid  = threadIdx.x;
    const int m0   = blockIdx.y << 7;
    const int n0   = blockIdx.x << 8;      // 256-wide n tile
    const int lane = tid & 31;
    const int warp = tid >> 5;
    const int wm   = (warp & 3) << 5;      // warp m offset (0..96)
    const int wn   = (warp >> 2) << 7;     // warp n offset (0 or 128)

    const __nv_bfloat16* srcs[4] = {
        Ah + (size_t)m0 * HH, Al + (size_t)m0 * HH,
        Wh + (size_t)n0 * HH, Wl + (size_t)n0 * HH };
    const int poff[4]  = {0, G1_PLANE_A, 2 * G1_PLANE_A, 2 * G1_PLANE_A + G1_PLANE_W};

    // load one k32 block (3072 16B chunks) into stage st
    auto issue = [&](int kt, int st) {
        __nv_bfloat16* sb = sm + st * G1_STAGE;
#pragma unroll
        for (int h = 0; h < 12; ++h) {
            int c    = tid + (h << 8);           // 0..3071
            int grow = c >> 2;                   // 0..767
            int col  = (c & 3) << 3;
            int p    = (grow < 256) ? (grow >> 7) : (2 + ((grow - 256) >> 8));
            int r    = (grow < 256) ? (grow & 127) : ((grow - 256) & 255);
            cp16(sb + poff[p] + r * G1_STRIDE + col,
                 srcs[p] + (size_t)r * HH + kt * 32 + col);
        }
        cp_commit();
    };

    float acc[2][16][4];
#pragma unroll
    for (int im = 0; im < 2; ++im)
#pragma unroll
        for (int j = 0; j < 16; ++j)
#pragma unroll
            for (int r = 0; r < 4; ++r) acc[im][j][r] = 0.f;

    issue(0, 0);
    issue(1, 1);

    const int arow  = lane & 15;
    const int acolb = (lane >> 4) << 3;
    const int brow  = ((lane & 16) >> 1) + (lane & 7);
    const int bcolb = ((lane >> 3) & 1) << 3;

    const int nk = HH / 32;                // 32
    for (int kt = 0; kt < nk; ++kt) {
        cp_wait1();
        __syncthreads();
        const __nv_bfloat16* st  = sm + (kt % 3) * G1_STAGE;
        const __nv_bfloat16* sAh = st;
        const __nv_bfloat16* sAl = st + G1_PLANE_A;
        const __nv_bfloat16* sWh = st + 2 * G1_PLANE_A;
        const __nv_bfloat16* sWl = st + 2 * G1_PLANE_A + G1_PLANE_W;
#pragma unroll
        for (int ks = 0; ks < 2; ++ks) {
            const int ko = ks << 4;
            unsigned aH[2][4], aL[2][4];
#pragma unroll
            for (int im = 0; im < 2; ++im) {
                int r = wm + (im << 4) + arow;
                ldsm4(aH[im], sAh + r * G1_STRIDE + ko + acolb);
                ldsm4(aL[im], sAl + r * G1_STRIDE + ko + acolb);
            }
#pragma unroll
            for (int ng = 0; ng < 8; ++ng) {
                int r = wn + (ng << 4) + brow;
                unsigned bh[4], bl[4];
                ldsm4(bh, sWh + r * G1_STRIDE + ko + bcolb);
                ldsm4(bl, sWl + r * G1_STRIDE + ko + bcolb);
#pragma unroll
                for (int im = 0; im < 2; ++im) {
                    mma16816(acc[im][ng * 2],     aH[im], bh[0], bh[1]);
                    mma16816(acc[im][ng * 2 + 1], aH[im], bh[2], bh[3]);
                    mma16816(acc[im][ng * 2],     aH[im], bl[0], bl[1]);
                    mma16816(acc[im][ng * 2 + 1], aH[im], bl[2], bl[3]);
                    mma16816(acc[im][ng * 2],     aL[im], bh[0], bh[1]);
                    mma16816(acc[im][ng * 2 + 1], aL[im], bh[2], bh[3]);
                }
            }
        }
        if (kt + 2 < nk) issue(kt + 2, (kt + 2) % 3);
        else             cp_commit();
    }

    // epilogue: bias + activation; act uniform per (n0, wn) 128-col block:
    // block 0:q(id) 1:k(sig) 2:g(sig) 3:v(tanh)
    const int nblk = (n0 + wn) >> 7;
    const int act  = (nblk == 0) ? 0 : ((nblk == 3) ? 2 : 1);
    const int r0     = m0 + wm + (lane >> 2);
    const int c0base = n0 + wn + ((lane & 3) << 1);
#pragma unroll
    for (int j = 0; j < 16; ++j) {
        int col = c0base + (j << 3);
        float b0 = bias[col], b1 = bias[col + 1];
#pragma unroll
        for (int im = 0; im < 2; ++im) {
            int rb = r0 + (im << 4);
            float v0 = acc[im][j][0] + b0, v1 = acc[im][j][1] + b1;
            float v2 = acc[im][j][2] + b0, v3 = acc[im][j][3] + b1;
            if (act == 1) {
                v0 = 1.f / (1.f + __expf(-v0)); v1 = 1.f / (1.f + __expf(-v1));
                v2 = 1.f / (1.f + __expf(-v2)); v3 = 1.f / (1.f + __expf(-v3));
            } else if (act == 2) {
                v0 = tanhf(v0); v1 = tanhf(v1); v2 = tanhf(v2); v3 = tanhf(v3);
            }
            *(float2*)(C + (size_t)rb * PP + col)       = make_float2(v0, v1);
            *(float2*)(C + (size_t)(rb + 8) * PP + col) = make_float2(v2, v3);
        }
    }
}

// ---------------------------------------------------------------------------
// Sequential scan, 8-step groups (halved barrier + shfl-chain overhead).
// Grid (batch=16, v-tile=8), 256 threads = 8 warps.
// Warp w owns v pair {v0+2w, v0+2w+1}; lane l owns k rows 4l..4l+3.
// 3-ring x 8 stages (37.5 KB static smem), 2 groups in flight (wait_group 1),
// refill issued immediately after the barrier (earliest overlap).
// ---------------------------------------------------------------------------
#define SC_GROUPS 3
#define SC_GS     8                        // steps per group
#define SC_STAGES (SC_GROUPS * SC_GS)      // 24

__global__ __launch_bounds__(256) void scan_kernel(
    const float* __restrict__ qkgv, float* __restrict__ obuf,
    float* __restrict__ cfin)
{
    const int b   = blockIdx.x;
    const int v0  = blockIdx.y << 4;
    const int tid = threadIdx.x;
    const int w   = tid >> 5;            // warp: v pair {2w, 2w+1} within tile
    const int l   = tid & 31;            // lane: k rows 4l..4l+3
    const int k0  = l << 2;

    __shared__ float s[SC_STAGES][400];  // [q:128 | k:128 | g:128 | v-tile:16]

    const float* base = qkgv + (size_t)b * TT * PP;
    float* ob = obuf + (size_t)b * TT * VV + v0 + (w << 1);

    float c[4][2];
#pragma unroll
    for (int i = 0; i < 4; ++i) { c[i][0] = 0.f; c[i][1] = 0.f; }

    // 100 copy threads x 16B per step
    const bool cpr = (tid < 100);
    const int goff = (tid < 96) ? (tid << 2) : (384 + v0 + ((tid - 96) << 2));
    const int soff = (tid < 96) ? (tid << 2) : (384 + ((tid - 96) << 2));

    auto issue_group = [&](int g) {
        if (cpr) {
            const int sb = (g % SC_GROUPS) * SC_GS;
            const float* p = base + (size_t)(g * SC_GS) * PP + goff;
#pragma unroll
            for (int i = 0; i < SC_GS; ++i)
                cp16(&s[sb + i][soff], p + (size_t)i * PP);
        }
        cp_commit();
    };

    issue_group(0);
    issue_group(1);

    const int NG = TT / SC_GS;           // 512 groups
    for (int g = 0; g < NG; ++g) {
        cp_wait1();                      // group g complete
        __syncthreads();

        // refill first: group g+2 -> slots of group g-1 (readers passed
        // this barrier; disjoint from slots of g being read now)
        if (g + 2 < NG) issue_group(g + 2);
        else            cp_commit();     // keep per-thread group counts uniform

        const int sb = (g % SC_GROUPS) * SC_GS;

        // batch-load all 8 steps' operands (one exposed LDS latency)
        float4 qr[SC_GS], kr[SC_GS], gr[SC_GS]; float2 vr[SC_GS];
#pragma unroll
        for (int i = 0; i < SC_GS; ++i) {
            const float* st = s[sb + i];
            qr[i] = *(const float4*)&st[k0];
            kr[i] = *(const float4*)&st[128 + k0];
            gr[i] = *(const float4*)&st[256 + k0];
            vr[i] = *(const float2*)&st[384 + (w << 1)];
        }

        float a0[SC_GS], a1[SC_GS];
#pragma unroll
        for (int i = 0; i < SC_GS; ++i) {
            const float vx = vr[i].x, vy = vr[i].y;
            c[0][0] = fmaf(c[0][0], gr[i].x, kr[i].x * vx);
            c[0][1] = fmaf(c[0][1], gr[i].x, kr[i].x * vy);
            c[1][0] = fmaf(c[1][0], gr[i].y, kr[i].y * vx);
            c[1][1] = fmaf(c[1][1], gr[i].y, kr[i].y * vy);
            c[2][0] = fmaf(c[2][0], gr[i].z, kr[i].z * vx);
            c[2][1] = fmaf(c[2][1], gr[i].z, kr[i].z * vy);
            c[3][0] = fmaf(c[3][0], gr[i].w, kr[i].w * vx);
            c[3][1] = fmaf(c[3][1], gr[i].w, kr[i].w * vy);
            float p0 = c[0][0] * qr[i].x;
            float p1 = c[0][1] * qr[i].x;
            p0 = fmaf(c[1][0], qr[i].y, p0);  p1 = fmaf(c[1][1], qr[i].y, p1);
            p0 = fmaf(c[2][0], qr[i].z, p0);  p1 = fmaf(c[2][1], qr[i].z, p1);
            p0 = fmaf(c[3][0], qr[i].w, p0);  p1 = fmaf(c[3][1], qr[i].w, p1);
            a0[i] = p0;  a1[i] = p1;
        }

        // 16 interleaved full-warp butterflies (reduce over k: all 32 lanes)
#pragma unroll
        for (int d = 1; d < 32; d <<= 1) {
#pragma unroll
            for (int i = 0; i < SC_GS; ++i) {
                a0[i] += __shfl_xor_sync(0xffffffffu, a0[i], d);
                a1[i] += __shfl_xor_sync(0xffffffffu, a1[i], d);
            }
        }
        if (l == 0) {
            const size_t t8 = (size_t)(g * SC_GS) * VV;
#pragma unroll
            for (int i = 0; i < SC_GS; ++i)
                *(float2*)&ob[t8 + (size_t)i * VV] = make_float2(a0[i], a1[i]);
        }
    }

    // c_final: (B, K, V). Thread owns k rows 4l..4l+3, v cols v0+2w..+1.
#pragma unroll
    for (int i = 0; i < 4; ++i)
        *(float2*)&cfin[((size_t)b * KK + (k0 + i)) * VV + v0 + (w << 1)] =
            make_float2(c[i][0], c[i][1]);
}

// ---------------------------------------------------------------------------
// GEMM2 (small): fp32 SIMT TN GEMM, 128x128 tile, BK=16.
// ---------------------------------------------------------------------------
__global__ __launch_bounds__(256) void gemm_tn(
    const float* __restrict__ A, const float* __restrict__ W,
    const float* __restrict__ bias, float* __restrict__ C,
    int M, int N, int Kd)
{
    __shared__ float As[2][16][136];
    __shared__ float Bs[2][16][136];

    const int tid = threadIdx.x;
    const int m0 = blockIdx.y << 7;
    const int n0 = blockIdx.x << 7;
    const int lr = tid >> 1;
    const int lc = (tid & 1) << 3;

    const float* Aptr = A + (size_t)(m0 + lr) * Kd + lc;
    const float* Wptr = W + (size_t)(n0 + lr) * Kd + lc;

    {
        float4 a0 = *(const float4*)Aptr;
        float4 a1 = *(const float4*)(Aptr + 4);
        float4 b0 = *(const float4*)Wptr;
        float4 b1 = *(const float4*)(Wptr + 4);
#pragma unroll
        for (int cc = 0; cc < 4; ++cc) {
            As[0][lc + cc][lr]     = ((const float*)&a0)[cc];
            As[0][lc + 4 + cc][lr] = ((const float*)&a1)[cc];
            Bs[0][lc + cc][lr]     = ((const float*)&b0)[cc];
            Bs[0][lc + 4 + cc][lr] = ((const float*)&b1)[cc];
        }
    }
    __syncthreads();

    const int ty  = tid >> 4;
    const int tx  = tid & 15;
    const int ar0 = ty << 2;
    const int bc0 = tx << 2;

    float acc[8][8];
#pragma unroll
    for (int i = 0; i < 8; ++i)
#pragma unroll
        for (int j = 0; j < 8; ++j) acc[i][j] = 0.f;

    const int nk = Kd >> 4;
    for (int kt = 0; kt < nk; ++kt) {
        const int buf = kt & 1;
        float4 pa0, pa1, pb0, pb1;
        const bool pf = (kt + 1) < nk;
        if (pf) {
            const float* Ap = Aptr + ((kt + 1) << 4);
            const float* Wp = Wptr + ((kt + 1) << 4);
            pa0 = *(const float4*)Ap;  pa1 = *(const float4*)(Ap + 4);
            pb0 = *(const float4*)Wp;  pb1 = *(const float4*)(Wp + 4);
        }
#pragma unroll
        for (int kk = 0; kk < 16; ++kk) {
            float4 a0 = *(const float4*)&As[buf][kk][ar0];
            float4 a1 = *(const float4*)&As[buf][kk][64 + ar0];
            float4 b0 = *(const float4*)&Bs[buf][kk][bc0];
            float4 b1 = *(const float4*)&Bs[buf][kk][64 + bc0];
            float af[8] = {a0.x,a0.y,a0.z,a0.w,a1.x,a1.y,a1.z,a1.w};
            float bf[8] = {b0.x,b0.y,b0.z,b0.w,b1.x,b1.y,b1.z,b1.w};
#pragma unroll
            for (int i = 0; i < 8; ++i)
#pragma unroll
                for (int j = 0; j < 8; ++j)
                    acc[i][j] = fmaf(af[i], bf[j], acc[i][j]);
        }
        if (pf) {
            const int nb = buf ^ 1;
#pragma unroll
            for (int cc = 0; cc < 4; ++cc) {
                As[nb][lc + cc][lr]     = ((const float*)&pa0)[cc];
                As[nb][lc + 4 + cc][lr] = ((const float*)&pa1)[cc];
                Bs[nb][lc + cc][lr]     = ((const float*)&pb0)[cc];
                Bs[nb][lc + 4 + cc][lr] = ((const float*)&pb1)[cc];
            }
        }
        __syncthreads();
    }

    float bv[8];
#pragma unroll
    for (int j = 0; j < 8; ++j) {
        int n = n0 + ((j < 4) ? (bc0 + j) : (64 + bc0 + (j - 4)));
        bv[j] = bias[n];
    }
#pragma unroll
    for (int i = 0; i < 8; ++i) {
        int m = m0 + ((i < 4) ? (ar0 + i) : (64 + ar0 + (i - 4)));
        float o[8];
#pragma unroll
        for (int j = 0; j < 8; ++j) o[j] = acc[i][j] + bv[j];
        float* cp = C + (size_t)m * N + n0;
        *(float4*)(cp + bc0)      = make_float4(o[0], o[1], o[2], o[3]);
        *(float4*)(cp + 64 + bc0) = make_float4(o[4], o[5], o[6], o[7]);
    }
}

// ---------------------------------------------------------------------------
extern "C" void kernel_launch(void* const* d_in, const int* in_sizes, int n_in,
                              void* d_out, int out_size)
{
    const float* hidden = (const float*)d_in[0];  // (B,T,H)
    const float* W_proj = (const float*)d_in[1];  // (3K+V, H)
    const float* b_proj = (const float*)d_in[2];  // (3K+V,)
    const float* W_out  = (const float*)d_in[3];  // (O, V)
    const float* b_out  = (const float*)d_in[4];  // (O,)
    float* out = (float*)d_out;

    float *qkgv, *obuf, *cdump;
    __nv_bfloat16 *ahi, *alo, *whi, *wlo;
    cudaGetSymbolAddress((void**)&qkgv,  g_qkgv);
    cudaGetSymbolAddress((void**)&obuf,  g_obuf);
    cudaGetSymbolAddress((void**)&cdump, g_cdump);
    cudaGetSymbolAddress((void**)&ahi,   g_ahi);
    cudaGetSymbolAddress((void**)&alo,   g_alo);
    cudaGetSymbolAddress((void**)&whi,   g_whi);
    cudaGetSymbolAddress((void**)&wlo,   g_wlo);

    const size_t out_main = (size_t)BB * TT * OO;
    const size_t out_full = out_main + (size_t)BB * KK * VV;
    float* cfin = ((size_t)out_size >= out_full) ? (out + out_main) : cdump;

    // 0) fp32 -> bf16 hi/lo splits
    {
        int n4 = (MM * HH) / 4;                     // 16,777,216
        cvt_hilo<<<(n4 + 255) / 256, 256>>>(hidden, ahi, alo, n4);
        int w4 = (PP * HH) / 4;                     // 131,072
        cvt_hilo<<<(w4 + 255) / 256, 256>>>(W_proj, whi, wlo, w4);
    }
    // 1) fused projection GEMM (mma.sync, 3-term bf16 split, N-fused tiles)
    {
        cudaFuncSetAttribute(gemm1_mma,
                             cudaFuncAttributeMaxDynamicSharedMemorySize, G1_SMEM);
        dim3 grid(PP / 256, MM / 128);              // (2, 512)
        gemm1_mma<<<grid, 256, G1_SMEM>>>(ahi, alo, whi, wlo, b_proj, qkgv);
    }
    // 2) sequential gated fast-weight scan (8-step groups)
    {
        dim3 grid(BB, VV / 16);                     // (16, 8)
        scan_kernel<<<grid, 256>>>(qkgv, obuf, cfin);
    }
    // 3) output projection
    {
        dim3 grid(OO / 128, MM / 128);              // (1, 512)
        gemm_tn<<<grid, 256>>>(obuf, W_out, b_out, out, MM, OO, VV);
    }
}